// round 3
// baseline (speedup 1.0000x reference)
#include <cuda_runtime.h>

// Soft-argmax: [4, 14, 1024, 1024] f32 NCHW -> [4, 2, 1024, 1024] f32
// Per pixel, two groups of 7 channels: softmax over 7, weighted sum with
// w_k = k - 3 (k = 0..6).

#define HW_   (1024 * 1024)
#define HW4_  (HW_ / 4)
#define NB_   4
#define NC_   14
#define NO_   2

__device__ __forceinline__ float softargmax7(const float* xs) {
    float m = xs[0];
#pragma unroll
    for (int k = 1; k < 7; k++) m = fmaxf(m, xs[k]);
    float s = 0.0f, t = 0.0f;
#pragma unroll
    for (int k = 0; k < 7; k++) {
        float e = __expf(xs[k] - m);
        s += e;
        t = fmaf((float)(k - 3), e, t);
    }
    return t * __frcp_rn(s);
}

__global__ __launch_bounds__(256) void softargmax_kernel(
    const float4* __restrict__ x, float4* __restrict__ out)
{
    int tid = blockIdx.x * blockDim.x + threadIdx.x;
    if (tid >= NB_ * HW4_) return;
    int b = tid >> 18;            // / HW4_ (HW4_ = 262144 = 2^18)
    int r = tid & (HW4_ - 1);

    const float4* xb = x + (size_t)b * NC_ * HW4_ + r;

    // Load all 14 channel float4s (4 pixels), unpack to registers.
    float v[NC_][4];
#pragma unroll
    for (int c = 0; c < NC_; c++) {
        float4 t = __ldg(&xb[(size_t)c * HW4_]);
        v[c][0] = t.x; v[c][1] = t.y; v[c][2] = t.z; v[c][3] = t.w;
    }

    float4* ob = out + (size_t)b * NO_ * HW4_ + r;

#pragma unroll
    for (int o = 0; o < NO_; o++) {
        float res[4];
#pragma unroll
        for (int j = 0; j < 4; j++) {
            float xs[7];
#pragma unroll
            for (int k = 0; k < 7; k++) xs[k] = v[o * 7 + k][j];
            res[j] = softargmax7(xs);
        }
        float4 ro;
        ro.x = res[0]; ro.y = res[1]; ro.z = res[2]; ro.w = res[3];
        ob[(size_t)o * HW4_] = ro;
    }
}

extern "C" void kernel_launch(void* const* d_in, const int* in_sizes, int n_in,
                              void* d_out, int out_size) {
    (void)in_sizes; (void)n_in; (void)out_size;
    const float4* x = (const float4*)d_in[0];
    float4* out = (float4*)d_out;
    int total = NB_ * HW4_;           // 1,048,576 threads
    int threads = 256;
    int blocks = (total + threads - 1) / threads;  // 4096
    softargmax_kernel<<<blocks, threads>>>(x, out);
}

// round 8
// speedup vs baseline: 1.0692x; 1.0692x over previous
#include <cuda_runtime.h>

// Soft-argmax: [4, 14, 1024, 1024] f32 NCHW -> [4, 2, 1024, 1024] f32
// Per pixel, two groups of 7 channels: softmax over 7, weighted sum with
// w_k = k - 3 (k = 0..6).
//
// R3/R4/R6: split the two channel groups into sequential phases to cut
// register pressure (64 -> ~40 regs), force 6 CTAs/SM for 75% occupancy, and
// use streaming loads/stores (no reuse; working set > L2).
// (R6 = identical resubmit; R3 hit "device busy" at harness init, R5/R6
// container failed to start. The change has never actually run.)

#define HW_   (1024 * 1024)
#define HW4_  (HW_ / 4)
#define NB_   4
#define NC_   14
#define NO_   2

__device__ __forceinline__ float softargmax7(const float xs[7]) {
    float m = xs[0];
#pragma unroll
    for (int k = 1; k < 7; k++) m = fmaxf(m, xs[k]);
    float s = 0.0f, t = 0.0f;
#pragma unroll
    for (int k = 0; k < 7; k++) {
        float e = __expf(xs[k] - m);
        s += e;
        t = fmaf((float)(k - 3), e, t);
    }
    return t * __frcp_rn(s);
}

__global__ void __launch_bounds__(256, 6) softargmax_kernel(
    const float4* __restrict__ x, float4* __restrict__ out)
{
    int tid = blockIdx.x * blockDim.x + threadIdx.x;
    if (tid >= NB_ * HW4_) return;
    int b = tid >> 18;            // / HW4_ (HW4_ = 262144 = 2^18)
    int r = tid & (HW4_ - 1);

    const float4* xb = x + (size_t)b * NC_ * HW4_ + r;
    float4*       ob = out + (size_t)b * NO_ * HW4_ + r;

#pragma unroll
    for (int o = 0; o < NO_; o++) {
        // Load this group's 7 channel float4s (4 pixels) — streaming.
        float4 c[7];
#pragma unroll
        for (int k = 0; k < 7; k++)
            c[k] = __ldcs(&xb[(size_t)(o * 7 + k) * HW4_]);

        float res[4];
#pragma unroll
        for (int j = 0; j < 4; j++) {
            float xs[7];
#pragma unroll
            for (int k = 0; k < 7; k++)
                xs[k] = ((const float*)&c[k])[j];
            res[j] = softargmax7(xs);
        }

        float4 ro;
        ro.x = res[0]; ro.y = res[1]; ro.z = res[2]; ro.w = res[3];
        __stcs(&ob[(size_t)o * HW4_], ro);
    }
}

extern "C" void kernel_launch(void* const* d_in, const int* in_sizes, int n_in,
                              void* d_out, int out_size) {
    (void)in_sizes; (void)n_in; (void)out_size;
    const float4* x = (const float4*)d_in[0];
    float4* out = (float4*)d_out;
    int total = NB_ * HW4_;           // 1,048,576 threads
    int threads = 256;
    int blocks = (total + threads - 1) / threads;  // 4096
    softargmax_kernel<<<blocks, threads>>>(x, out);
}